// round 11
// baseline (speedup 1.0000x reference)
#include <cuda_runtime.h>
#include <cstdint>

// Problem constants
#define Bq   128        // batch
#define Nn   100000     // bank size
#define Dd   128        // feature dim
#define ROWS 129        // memory_da row stride (label + 128 feats)
#define TILE_N 64
#define NTILES 1563     // ceil(100000/64)

// exp(dot/T) = 2^(dot * log2(e)/T)
#define KLOG2 20.609929155556620f

// smem layout (floats)
#define XS_OFF   0            // [128][132]
#define FS_OFF   16896        // [128][68]
#define LAB_OFF  25600        // [64]
#define BLAB_OFF 25664        // [128]
#define SMEM_FLOATS 25792
#define SMEM_BYTES  (SMEM_FLOATS * 4)

// scratch (no allocation allowed -> device globals)
__device__ float g_Zpart[NTILES * Bq];
__device__ float g_invZ[Bq];

// ---------------------------------------------------------------------------
// FFMA-only exp2: 2^t for |t| <= ~40, rel err ~2e-6
// ---------------------------------------------------------------------------
__device__ __forceinline__ float exp2_fast(float t) {
    float r = __fadd_rn(t, 12582912.0f);              // round to int (magic 1.5*2^23)
    float f = __fsub_rn(t, __fsub_rn(r, 12582912.0f)); // f in [-0.5, 0.5]
    int   n = __float_as_int(r) - 0x4B400000;
    float p = 0.00133335581f;
    p = fmaf(p, f, 0.00961812910f);
    p = fmaf(p, f, 0.05550410866f);
    p = fmaf(p, f, 0.24022650696f);
    p = fmaf(p, f, 0.69314718056f);
    p = fmaf(p, f, 1.0f);
    return __int_as_float(__float_as_int(p) + (n << 23));
}

// ---------------------------------------------------------------------------
// Main kernel: per CTA, a 128(b) x 64(n) tile of E = exp(x.feats^T / T),
// the matching idx_mask tile, and per-b partial sums for Z.
// FFMA2 (fma.rn.f32x2) microkernel, pairs along b.
// ---------------------------------------------------------------------------
__global__ void __launch_bounds__(256, 2)
nce_main(const float* __restrict__ x,
         const int*   __restrict__ labels,
         const float* __restrict__ mda,
         float* __restrict__ outE,
         float* __restrict__ outM)
{
    extern __shared__ float sm[];
    float* xs   = sm + XS_OFF;    // transposed x: xs[d*132 + b]
    float* fs   = sm + FS_OFF;    // transposed feats tile: fs[d*68 + n]
    float* labf = sm + LAB_OFF;   // tile row labels
    float* blab = sm + BLAB_OFF;  // batch labels as float

    const int t  = threadIdx.x;
    const int nb = blockIdx.x * TILE_N;

    // ---- stage x (coalesced LDG, transposed STS) ----
    #pragma unroll
    for (int i = 0; i < 64; i++) {
        int idx = i * 256 + t;
        int d = idx & 127, b = idx >> 7;
        xs[d * 132 + b] = x[b * Dd + d];
    }
    // ---- stage feats tile ----
    #pragma unroll
    for (int i = 0; i < 32; i++) {
        int idx = i * 256 + t;
        int d = idx & 127, n = idx >> 7;
        int gn = nb + n;
        fs[d * 68 + n] = (gn < Nn) ? mda[(size_t)gn * ROWS + 1 + d] : 0.0f;
    }
    if (t < TILE_N) {
        int gn = nb + t;
        labf[t] = (gn < Nn) ? mda[(size_t)gn * ROWS] : -1.0f;
    }
    if (t < Bq) blab[t] = (float)labels[t];
    __syncthreads();

    const int tx = t & 15, ty = t >> 4;
    const int b0 = ty * 8, n0 = tx * 4;

    uint32_t xs_sa = (uint32_t)__cvta_generic_to_shared(xs) + (uint32_t)b0 * 4u;
    uint32_t fs_sa = (uint32_t)__cvta_generic_to_shared(fs) + (uint32_t)n0 * 4u;

    unsigned long long acc[16];
    #pragma unroll
    for (int i = 0; i < 16; i++) acc[i] = 0ULL;

    #pragma unroll 8
    for (int k = 0; k < 128; k++) {
        unsigned long long a2[4];
        uint32_t aa = xs_sa + (uint32_t)k * 528u;      // 132 floats * 4B
        asm("ld.shared.b64 %0, [%1];"     : "=l"(a2[0]) : "r"(aa));
        asm("ld.shared.b64 %0, [%1+8];"   : "=l"(a2[1]) : "r"(aa));
        asm("ld.shared.b64 %0, [%1+16];"  : "=l"(a2[2]) : "r"(aa));
        asm("ld.shared.b64 %0, [%1+24];"  : "=l"(a2[3]) : "r"(aa));

        float bx, by, bz, bw;
        uint32_t fa = fs_sa + (uint32_t)k * 272u;      // 68 floats * 4B
        asm("ld.shared.v4.f32 {%0,%1,%2,%3}, [%4];"
            : "=f"(bx), "=f"(by), "=f"(bz), "=f"(bw) : "r"(fa));

        unsigned long long b2[4];
        asm("mov.b64 %0, {%1,%2};" : "=l"(b2[0]) : "f"(bx), "f"(bx));
        asm("mov.b64 %0, {%1,%2};" : "=l"(b2[1]) : "f"(by), "f"(by));
        asm("mov.b64 %0, {%1,%2};" : "=l"(b2[2]) : "f"(bz), "f"(bz));
        asm("mov.b64 %0, {%1,%2};" : "=l"(b2[3]) : "f"(bw), "f"(bw));

        #pragma unroll
        for (int bp = 0; bp < 4; bp++)
            #pragma unroll
            for (int n = 0; n < 4; n++)
                asm("fma.rn.f32x2 %0, %1, %2, %0;"
                    : "+l"(acc[bp * 4 + n]) : "l"(a2[bp]), "l"(b2[n]));
    }

    // ---- epilogue: exp, partial sums, stores ----
    float ev[8][4];
    #pragma unroll
    for (int bp = 0; bp < 4; bp++) {
        #pragma unroll
        for (int n = 0; n < 4; n++) {
            float lo, hi;
            asm("mov.b64 {%0,%1}, %2;" : "=f"(lo), "=f"(hi) : "l"(acc[bp * 4 + n]));
            ev[2 * bp + 0][n] = exp2_fast(lo * KLOG2);
            ev[2 * bp + 1][n] = exp2_fast(hi * KLOG2);
        }
    }

    float vmask[4];
    #pragma unroll
    for (int n = 0; n < 4; n++) vmask[n] = (nb + n0 + n < Nn) ? 1.0f : 0.0f;

    float rs[8];
    #pragma unroll
    for (int lb = 0; lb < 8; lb++) {
        float s = 0.0f;
        #pragma unroll
        for (int n = 0; n < 4; n++) s += ev[lb][n] * vmask[n];
        rs[lb] = s;
    }

    // reduce across the 16 tx lanes sharing each b (xor within 16-lane half)
    #pragma unroll
    for (int lb = 0; lb < 8; lb++) {
        float v = rs[lb];
        v += __shfl_xor_sync(0xFFFFFFFFu, v, 1);
        v += __shfl_xor_sync(0xFFFFFFFFu, v, 2);
        v += __shfl_xor_sync(0xFFFFFFFFu, v, 4);
        v += __shfl_xor_sync(0xFFFFFFFFu, v, 8);
        if (tx == 0) g_Zpart[blockIdx.x * Bq + b0 + lb] = v;
    }

    // stores (unnormalized E + mask); vectorized unless tail tile
    const size_t colbase = (size_t)nb + n0;
    if (nb + TILE_N <= Nn) {
        #pragma unroll
        for (int lb = 0; lb < 8; lb++) {
            int gb = b0 + lb;
            size_t off = (size_t)gb * Nn + colbase;
            float4 o; o.x = ev[lb][0]; o.y = ev[lb][1]; o.z = ev[lb][2]; o.w = ev[lb][3];
            *reinterpret_cast<float4*>(outE + off) = o;
            float bl = blab[gb];
            float4 m;
            m.x = (labf[n0 + 0] == bl) ? 1.0f : 0.0f;
            m.y = (labf[n0 + 1] == bl) ? 1.0f : 0.0f;
            m.z = (labf[n0 + 2] == bl) ? 1.0f : 0.0f;
            m.w = (labf[n0 + 3] == bl) ? 1.0f : 0.0f;
            *reinterpret_cast<float4*>(outM + off) = m;
        }
    } else {
        #pragma unroll
        for (int lb = 0; lb < 8; lb++) {
            int gb = b0 + lb;
            float bl = blab[gb];
            #pragma unroll
            for (int n = 0; n < 4; n++) {
                if (colbase + n < (size_t)Nn) {
                    size_t off = (size_t)gb * Nn + colbase + n;
                    outE[off] = ev[lb][n];
                    outM[off] = (labf[n0 + n] == bl) ? 1.0f : 0.0f;
                }
            }
        }
    }
}

// ---------------------------------------------------------------------------
// Reduce partials -> invZ[b] = 1 / sum_n exp(.)
// ---------------------------------------------------------------------------
__global__ void nce_reduce()
{
    __shared__ float s[8][Bq];
    int t = threadIdx.x;
    int b = t & 127, c = t >> 7;
    float sum = 0.0f;
    for (int j = c; j < NTILES; j += 8)
        sum += g_Zpart[j * Bq + b];
    s[c][b] = sum;
    __syncthreads();
    if (t < Bq) {
        float z = 0.0f;
        #pragma unroll
        for (int c2 = 0; c2 < 8; c2++) z += s[c2][t];
        g_invZ[t] = 1.0f / z;
    }
}

// ---------------------------------------------------------------------------
// Scale E rows by invZ[b] (pure bandwidth)
// ---------------------------------------------------------------------------
__global__ void nce_scale(float* __restrict__ out)
{
    int b = blockIdx.y;
    float inv = g_invZ[b];
    int i = blockIdx.x * blockDim.x + threadIdx.x;
    if (i < Nn / 4) {
        float4* row = reinterpret_cast<float4*>(out) + (size_t)b * (Nn / 4);
        float4 v = row[i];
        v.x *= inv; v.y *= inv; v.z *= inv; v.w *= inv;
        row[i] = v;
    }
}

// ---------------------------------------------------------------------------
// launch
// inputs: 0=x (128x128 f32), 1=y (128 i32, unused), 2=labels (128 i32),
//         3=memory_da (100000x129 f32), 4=memory (unused)
// output: concat(out.flatten(), idx_mask.flatten()) as f32, 2*128*100000 elems
// ---------------------------------------------------------------------------
extern "C" void kernel_launch(void* const* d_in, const int* in_sizes, int n_in,
                              void* d_out, int out_size)
{
    (void)in_sizes; (void)n_in;
    const float* x      = (const float*)d_in[0];
    const int*   labels = (const int*)  d_in[2];
    const float* mda    = (const float*)d_in[3];
    float* out = (float*)d_out;
    size_t half = (size_t)out_size / 2;   // = B*N = 12,800,000

    cudaFuncSetAttribute(nce_main, cudaFuncAttributeMaxDynamicSharedMemorySize,
                         SMEM_BYTES);

    nce_main<<<NTILES, 256, SMEM_BYTES>>>(x, labels, mda, out, out + half);
    nce_reduce<<<1, 1024>>>();
    nce_scale<<<dim3((Nn / 4 + 255) / 256, Bq), 256>>>(out);
}